// round 14
// baseline (speedup 1.0000x reference)
#include <cuda_runtime.h>
#include <cuda_fp16.h>
#include <cstdint>

#define B_SZ 4096
#define NI   512
#define NO   512
#define KK   (NI*8)          // 4096

// ---------------- scratch (device globals; no allocation allowed) ----------
__device__ __half g_a[(size_t)B_SZ * KK];   // 32 MB
__device__ __half g_b[(size_t)NO * KK];     //  4 MB

// ---------------- helpers ---------------------------------------------------
__device__ __forceinline__ uint32_t smem_u32(const void* p) {
    uint32_t a;
    asm("{ .reg .u64 t; cvta.to.shared.u64 t, %1; cvt.u32.u64 %0, t; }"
        : "=r"(a) : "l"(p));
    return a;
}
__device__ __forceinline__ void cp16(uint32_t dst, const void* src) {
    asm volatile("cp.async.cg.shared.global [%0], [%1], 16;"
                 :: "r"(dst), "l"(src));
}
__device__ __forceinline__ void ldsm4(uint32_t* r, uint32_t addr) {
    asm volatile("ldmatrix.sync.aligned.m8n8.x4.shared.b16 {%0,%1,%2,%3}, [%4];"
                 : "=r"(r[0]), "=r"(r[1]), "=r"(r[2]), "=r"(r[3]) : "r"(addr));
}
__device__ __forceinline__ void mma16816(float* d, const uint32_t* a,
                                         uint32_t b0, uint32_t b1) {
    asm volatile(
        "mma.sync.aligned.m16n8k16.row.col.f32.f16.f16.f32 "
        "{%0,%1,%2,%3}, {%4,%5,%6,%7}, {%8,%9}, {%0,%1,%2,%3};"
        : "+f"(d[0]), "+f"(d[1]), "+f"(d[2]), "+f"(d[3])
        : "r"(a[0]), "r"(a[1]), "r"(a[2]), "r"(a[3]), "r"(b0), "r"(b1));
}

// fast tanh: rel err ~1e-6, far below fp16 quantization (2^-11)
__device__ __forceinline__ float fast_tanh(float x) {
    float xc = fminf(fmaxf(x, -9.0f), 9.0f);
    float e  = __expf(2.0f * xc);
    return 1.0f - __fdividef(2.0f, e + 1.0f);
}

__device__ __forceinline__ void jacobi8_to_half(float t, __half* h) {
    float p[8];
    p[0] = 1.0f;
    p[1] = 2.0f * t;
    p[2] = 1.875f      * t * p[1] - 0.75f       * p[0];
    p[3] = 1.8666667f  * t * p[2] - 0.8f        * p[1];
    p[4] = 1.875f      * t * p[3] - 0.8333333f  * p[2];
    p[5] = 1.8857143f  * t * p[4] - 0.85714287f * p[3];
    p[6] = 1.8958334f  * t * p[5] - 0.875f      * p[4];
    p[7] = 1.9047619f  * t * p[6] - 0.8888889f  * p[5];
    #pragma unroll
    for (int d = 0; d < 8; ++d) h[d] = __float2half_rn(p[d]);
}

// ---------------- phase 1: fused expand + coef convert ----------------------
#define NBLK_A 2048
__global__ __launch_bounds__(256) void prep_kernel(const float* __restrict__ x,
                                                   const float* __restrict__ coef) {
    if (blockIdx.x < NBLK_A) {
        int base = blockIdx.x * 1024 + threadIdx.x;
        float t[4];
        #pragma unroll
        for (int e = 0; e < 4; ++e) t[e] = fast_tanh(x[base + e * 256]);
        #pragma unroll
        for (int e = 0; e < 4; ++e) {
            __half h[8];
            jacobi8_to_half(t[e], h);
            *reinterpret_cast<uint4*>(g_a + (size_t)(base + e * 256) * 8) =
                *reinterpret_cast<uint4*>(h);
        }
    } else {
        int base = (blockIdx.x - NBLK_A) * 1024 + threadIdx.x;
        #pragma unroll
        for (int e = 0; e < 4; ++e) {
            int idx = base + e * 256;
            float p[8];
            const float4* s = reinterpret_cast<const float4*>(coef + (size_t)idx * 8);
            *reinterpret_cast<float4*>(p)     = s[0];
            *reinterpret_cast<float4*>(p + 4) = s[1];
            __half h[8];
            #pragma unroll
            for (int d = 0; d < 8; ++d) h[d] = __float2half_rn(p[d]);
            *reinterpret_cast<uint4*>(g_b + (size_t)idx * 8) =
                *reinterpret_cast<uint4*>(h);
        }
    }
}

// ---------------- phase 2: split-K-in-CTA fp16 warp-MMA GEMM ----------------
// out[4096,512] = A[4096,4096] @ B[512,4096]^T, fp32 accumulate.
// CTA = 128x128 tile, 256 threads = 8 warps.
//   warp-group 0 (wid 0-3): K[0, 2048)       2x2 warps of 64x64
//   warp-group 1 (wid 4-7): K[2048, 4096)    2x2 warps of 64x64
// => 2 MMA warps per SMSP (overlap) with 64x64-tile LDSM economy.
// Stage = [A_g0|B_g0|A_g1|B_g1] 16KB each = 64KB; 3 stages = 192KB.
// Final: group 1 accs pass through smem, group 0 adds + stores.
#define BKH 64
#define TILE_BYTES 16384
#define GRP_BYTES  32768
#define STAGE_BYTES 65536
#define NSTAGE 3
#define KSPLIT 2048
#define SMEM_DYN (1024 + NSTAGE * STAGE_BYTES)

// swizzled offset inside a [rows][64 fp16] tile: 128B rows, 16B chunks
__device__ __forceinline__ uint32_t swoff(int row, int chunk) {
    return (uint32_t)(row * 128 + ((chunk ^ (row & 7)) * 16));
}

// load one 128-row x 64-fp16 tile (16KB) with cp.async, 256 threads
__device__ __forceinline__ void load_tile(uint32_t sdst,
                                          const __half* gsrc, int tid) {
    #pragma unroll
    for (int t = 0; t < 4; ++t) {
        int idx = t * 256 + tid;           // 1024 chunks of 16B
        int row = idx >> 3, ch = idx & 7;
        cp16(sdst + swoff(row, ch),
             (const char*)(gsrc + (size_t)row * KK) + ch * 16);
    }
}
// load a full stage: both groups' A and B k-tiles (k0 = iter*64)
__device__ __forceinline__ void load_stage(uint32_t sb, const __half* A,
                                           const __half* B, int k0, int tid) {
    load_tile(sb,                  A + k0,          tid);
    load_tile(sb + TILE_BYTES,     B + k0,          tid);
    load_tile(sb + GRP_BYTES,      A + k0 + KSPLIT, tid);
    load_tile(sb + GRP_BYTES + TILE_BYTES, B + k0 + KSPLIT, tid);
}

__global__ __launch_bounds__(256, 1)
void kan_gemm(float* __restrict__ out) {
    extern __shared__ char smraw[];
    uint32_t sbase = (smem_u32(smraw) + 1023) & ~1023u;

    const int tid  = threadIdx.x;
    const int lane = tid & 31;
    const int wid  = tid >> 5;          // 0..7
    const int kg   = wid >> 2;          // 0/1: K-split group
    const int w    = wid & 3;           // warp within group
    const int wm   = w >> 1;            // 0..1  (64-row slice)
    const int wn   = w & 1;             // 0..1  (64-col slice)
    const int brow = blockIdx.y * 128;
    const int bcol = blockIdx.x * 128;

    const __half* A = g_a + (size_t)brow * KK;
    const __half* B = g_b + (size_t)bcol * KK;

    float acc[4][8][4];
    #pragma unroll
    for (int i = 0; i < 4; ++i)
        #pragma unroll
        for (int j = 0; j < 8; ++j)
            #pragma unroll
            for (int c = 0; c < 4; ++c) acc[i][j][c] = 0.0f;

    // ldmatrix per-lane row / chunk-half mapping
    const int ar  = lane & 15;                        // A row within m16 tile
    const int ac  = lane >> 4;                        // A k-chunk half (0/1)
    const int br0 = ((lane >> 4) << 3) + (lane & 7);  // B row within n16 pair
    const int bc  = (lane >> 3) & 1;                  // B k-chunk half (0/1)

    // prologue: stages 0,1
    #pragma unroll
    for (int t = 0; t < NSTAGE - 1; ++t) {
        load_stage(sbase + t * STAGE_BYTES, A, B, t * BKH, tid);
        asm volatile("cp.async.commit_group;" ::: "memory");
    }

    const int NIT = KSPLIT / BKH;        // 32
    for (int kt = 0; kt < NIT; ++kt) {
        asm volatile("cp.async.wait_group %0;" :: "n"(NSTAGE - 2) : "memory");
        __syncthreads();

        // prefetch stage kt+2
        int nk = kt + NSTAGE - 1;
        if (nk < NIT) {
            load_stage(sbase + (nk % NSTAGE) * STAGE_BYTES, A, B, nk * BKH, tid);
        }
        asm volatile("cp.async.commit_group;" ::: "memory");

        // compute from stage kt%3, own group's half
        uint32_t sg = sbase + (kt % NSTAGE) * STAGE_BYTES + kg * GRP_BYTES;
        uint32_t aB = sg, bB = sg + TILE_BYTES;

        #pragma unroll
        for (int s = 0; s < 4; ++s) {            // 4 k16 steps in BK=64
            uint32_t a[4][4];
            #pragma unroll
            for (int mt = 0; mt < 4; ++mt)
                ldsm4(a[mt], aB + swoff(wm * 64 + mt * 16 + ar, s * 2 + ac));
            uint32_t b[4][4];
            #pragma unroll
            for (int p = 0; p < 4; ++p)
                ldsm4(b[p], bB + swoff(wn * 64 + p * 16 + br0, s * 2 + bc));
            #pragma unroll
            for (int mt = 0; mt < 4; ++mt)
                #pragma unroll
                for (int p = 0; p < 4; ++p) {
                    mma16816(acc[mt][2*p],   a[mt], b[p][0], b[p][1]);
                    mma16816(acc[mt][2*p+1], a[mt], b[p][2], b[p][3]);
                }
        }
        __syncthreads();
    }

    // ---- cross-group reduction through smem (reg-major, conflict-free) ----
    // red[r][col]: r = flattened acc index (0..127), col = w*32 + lane (0..127)
    float* red = reinterpret_cast<float*>(smraw);   // 64KB, reuse stage smem
    const int col = w * 32 + lane;
    __syncthreads();
    if (kg == 1) {
        #pragma unroll
        for (int mt = 0; mt < 4; ++mt)
            #pragma unroll
            for (int nt = 0; nt < 8; ++nt)
                #pragma unroll
                for (int c = 0; c < 4; ++c)
                    red[(mt * 32 + nt * 4 + c) * 128 + col] = acc[mt][nt][c];
    }
    __syncthreads();
    if (kg == 0) {
        #pragma unroll
        for (int mt = 0; mt < 4; ++mt)
            #pragma unroll
            for (int nt = 0; nt < 8; ++nt)
                #pragma unroll
                for (int c = 0; c < 4; ++c)
                    acc[mt][nt][c] += red[(mt * 32 + nt * 4 + c) * 128 + col];

        // epilogue: c-fragment layout -> float2 stores
        const int r0 = brow + wm * 64 + (lane >> 2);
        const int c0 = bcol + wn * 64 + (lane & 3) * 2;
        #pragma unroll
        for (int mt = 0; mt < 4; ++mt) {
            #pragma unroll
            for (int nt = 0; nt < 8; ++nt) {
                float* p = out + (size_t)(r0 + mt * 16) * NO + c0 + nt * 8;
                *reinterpret_cast<float2*>(p) =
                    make_float2(acc[mt][nt][0], acc[mt][nt][1]);
                *reinterpret_cast<float2*>(p + 8 * NO) =
                    make_float2(acc[mt][nt][2], acc[mt][nt][3]);
            }
        }
    }
}

// ---------------- launcher ---------------------------------------------------
extern "C" void kernel_launch(void* const* d_in, const int* in_sizes, int n_in,
                              void* d_out, int out_size)
{
    const float* x    = (const float*)d_in[0];   // [4096, 512]
    const float* coef = (const float*)d_in[1];   // [512, 512, 8]
    float* out        = (float*)d_out;           // [4096, 512]

    cudaFuncSetAttribute(kan_gemm, cudaFuncAttributeMaxDynamicSharedMemorySize,
                         SMEM_DYN);

    prep_kernel<<<NBLK_A + (NO * NI) / 1024, 256>>>(x, coef);

    dim3 grid(NO / 128, B_SZ / 128);             // (4, 32)
    kan_gemm<<<grid, 256, SMEM_DYN>>>(out);
}

// round 15
// speedup vs baseline: 1.0146x; 1.0146x over previous
#include <cuda_runtime.h>
#include <cuda_fp16.h>
#include <cstdint>

#define B_SZ 4096
#define NI   512
#define NO   512
#define KK   (NI*8)          // 4096

// ---------------- scratch (device globals; no allocation allowed) ----------
__device__ __half g_a[(size_t)B_SZ * KK];   // 32 MB
__device__ __half g_b[(size_t)NO * KK];     //  4 MB

// ---------------- helpers ---------------------------------------------------
__device__ __forceinline__ uint32_t smem_u32(const void* p) {
    uint32_t a;
    asm("{ .reg .u64 t; cvta.to.shared.u64 t, %1; cvt.u32.u64 %0, t; }"
        : "=r"(a) : "l"(p));
    return a;
}
__device__ __forceinline__ void cp16(uint32_t dst, const void* src) {
    asm volatile("cp.async.cg.shared.global [%0], [%1], 16;"
                 :: "r"(dst), "l"(src));
}
__device__ __forceinline__ void ldsm4(uint32_t* r, uint32_t addr) {
    asm volatile("ldmatrix.sync.aligned.m8n8.x4.shared.b16 {%0,%1,%2,%3}, [%4];"
                 : "=r"(r[0]), "=r"(r[1]), "=r"(r[2]), "=r"(r[3]) : "r"(addr));
}
__device__ __forceinline__ void mma16816(float* d, const uint32_t* a,
                                         uint32_t b0, uint32_t b1) {
    asm volatile(
        "mma.sync.aligned.m16n8k16.row.col.f32.f16.f16.f32 "
        "{%0,%1,%2,%3}, {%4,%5,%6,%7}, {%8,%9}, {%0,%1,%2,%3};"
        : "+f"(d[0]), "+f"(d[1]), "+f"(d[2]), "+f"(d[3])
        : "r"(a[0]), "r"(a[1]), "r"(a[2]), "r"(a[3]), "r"(b0), "r"(b1));
}

// fast tanh: rel err ~1e-6, far below fp16 quantization (2^-11)
__device__ __forceinline__ float fast_tanh(float x) {
    float xc = fminf(fmaxf(x, -9.0f), 9.0f);
    float e  = __expf(2.0f * xc);
    return 1.0f - __fdividef(2.0f, e + 1.0f);
}

__device__ __forceinline__ void jacobi8_to_half(float t, __half* h) {
    float p[8];
    p[0] = 1.0f;
    p[1] = 2.0f * t;
    p[2] = 1.875f      * t * p[1] - 0.75f       * p[0];
    p[3] = 1.8666667f  * t * p[2] - 0.8f        * p[1];
    p[4] = 1.875f      * t * p[3] - 0.8333333f  * p[2];
    p[5] = 1.8857143f  * t * p[4] - 0.85714287f * p[3];
    p[6] = 1.8958334f  * t * p[5] - 0.875f      * p[4];
    p[7] = 1.9047619f  * t * p[6] - 0.8888889f  * p[5];
    #pragma unroll
    for (int d = 0; d < 8; ++d) h[d] = __float2half_rn(p[d]);
}

// ---------------- phase 1: fused expand + coef convert ----------------------
#define NBLK_A 2048
__global__ __launch_bounds__(256) void prep_kernel(const float* __restrict__ x,
                                                   const float* __restrict__ coef) {
    if (blockIdx.x < NBLK_A) {
        int base = blockIdx.x * 1024 + threadIdx.x;
        float t[4];
        #pragma unroll
        for (int e = 0; e < 4; ++e) t[e] = fast_tanh(x[base + e * 256]);
        #pragma unroll
        for (int e = 0; e < 4; ++e) {
            __half h[8];
            jacobi8_to_half(t[e], h);
            *reinterpret_cast<uint4*>(g_a + (size_t)(base + e * 256) * 8) =
                *reinterpret_cast<uint4*>(h);
        }
    } else {
        int base = (blockIdx.x - NBLK_A) * 1024 + threadIdx.x;
        #pragma unroll
        for (int e = 0; e < 4; ++e) {
            int idx = base + e * 256;
            float p[8];
            const float4* s = reinterpret_cast<const float4*>(coef + (size_t)idx * 8);
            *reinterpret_cast<float4*>(p)     = s[0];
            *reinterpret_cast<float4*>(p + 4) = s[1];
            __half h[8];
            #pragma unroll
            for (int d = 0; d < 8; ++d) h[d] = __float2half_rn(p[d]);
            *reinterpret_cast<uint4*>(g_b + (size_t)idx * 8) =
                *reinterpret_cast<uint4*>(h);
        }
    }
}

// ---------------- phase 2: fp16 warp-MMA GEMM, 64x64 tiles, frag pipeline ---
// out[4096,512] = A[4096,4096] @ B[512,4096]^T, fp32 accumulate.
// BM=BN=128, BK=128, 128 threads = 4 warps, warp tile 64x64 (2x2 grid).
// Fragments for k-step s+1 are LDSM'd while HMMAs of step s execute
// (double-buffered), hiding LDS latency in the 1-warp/SMSP regime.
#define BKH 128
#define SUB_BYTES 16384
#define STAGE_BYTES 65536
#define NSTAGE 3
#define SMEM_DYN (1024 + NSTAGE * STAGE_BYTES)

// swizzled offset inside a [rows][64 fp16] subtile: 128B rows, 16B chunks
__device__ __forceinline__ uint32_t swoff(int row, int chunk) {
    return (uint32_t)(row * 128 + ((chunk ^ (row & 7)) * 16));
}

// load one 128-row x 64-fp16 subtile (16KB) with cp.async, 128 threads
__device__ __forceinline__ void load_sub(uint32_t sdst,
                                         const __half* gsrc, int tid) {
    #pragma unroll
    for (int t = 0; t < 8; ++t) {
        int idx = t * 128 + tid;           // 1024 chunks of 16B
        int row = idx >> 3, ch = idx & 7;
        cp16(sdst + swoff(row, ch),
             (const char*)(gsrc + (size_t)row * KK) + ch * 16);
    }
}
__device__ __forceinline__ void load_stage(uint32_t sb, const __half* A,
                                           const __half* B, int k0, int tid) {
    load_sub(sb,                 A + k0,      tid);
    load_sub(sb + SUB_BYTES,     A + k0 + 64, tid);
    load_sub(sb + 2 * SUB_BYTES, B + k0,      tid);
    load_sub(sb + 3 * SUB_BYTES, B + k0 + 64, tid);
}

__global__ __launch_bounds__(128)
void kan_gemm(float* __restrict__ out) {
    extern __shared__ char smraw[];
    uint32_t sbase = (smem_u32(smraw) + 1023) & ~1023u;

    const int tid  = threadIdx.x;
    const int lane = tid & 31;
    const int wid  = tid >> 5;          // 0..3
    const int wm   = wid >> 1;          // 0..1  (64-row slice)
    const int wn   = wid & 1;           // 0..1  (64-col slice)
    const int brow = blockIdx.y * 128;
    const int bcol = blockIdx.x * 128;

    const __half* A = g_a + (size_t)brow * KK;
    const __half* B = g_b + (size_t)bcol * KK;

    float acc[4][8][4];
    #pragma unroll
    for (int i = 0; i < 4; ++i)
        #pragma unroll
        for (int j = 0; j < 8; ++j)
            #pragma unroll
            for (int c = 0; c < 4; ++c) acc[i][j][c] = 0.0f;

    // ldmatrix per-lane row / chunk-half mapping
    const int ar  = lane & 15;                        // A row within m16 tile
    const int ac  = lane >> 4;                        // A k-chunk half (0/1)
    const int br0 = ((lane >> 4) << 3) + (lane & 7);  // B row within n16 pair
    const int bc  = (lane >> 3) & 1;                  // B k-chunk half (0/1)

    // per-warp base row offsets into the subtiles
    const int arow = wm * 64 + ar;
    const int brow2 = wn * 64 + br0;

    // prologue: stages 0,1
    #pragma unroll
    for (int t = 0; t < NSTAGE - 1; ++t) {
        load_stage(sbase + t * STAGE_BYTES, A, B, t * BKH, tid);
        asm volatile("cp.async.commit_group;" ::: "memory");
    }

    const int NIT = KK / BKH;            // 32
    for (int kt = 0; kt < NIT; ++kt) {
        asm volatile("cp.async.wait_group %0;" :: "n"(NSTAGE - 2) : "memory");
        __syncthreads();

        uint32_t sb = sbase + (kt % NSTAGE) * STAGE_BYTES;

        // double-buffered fragments: preload k-step 0
        uint32_t af[2][4][4], bf[2][4][4];
        #pragma unroll
        for (int mt = 0; mt < 4; ++mt)
            ldsm4(af[0][mt], sb + swoff(arow + mt * 16, ac));
        #pragma unroll
        for (int p = 0; p < 4; ++p)
            ldsm4(bf[0][p], sb + 2 * SUB_BYTES + swoff(brow2 + p * 16, bc));

        // issue prefetch of stage kt+2 now: its 32 cp.async issues cover
        // the LDS latency of the step-0 fragments.
        int nk = kt + NSTAGE - 1;
        if (nk < NIT) {
            load_stage(sbase + (nk % NSTAGE) * STAGE_BYTES, A, B, nk * BKH, tid);
        }
        asm volatile("cp.async.commit_group;" ::: "memory");

        // 8 k16 steps (h = step>>2 selects 64-col half, s = step&3)
        #pragma unroll
        for (int step = 0; step < 8; ++step) {
            const int cur = step & 1;
            const int nxt = cur ^ 1;
            if (step < 7) {
                const int ns = step + 1;
                const int nh = ns >> 2, nss = ns & 3;
                uint32_t aB = sb + nh * SUB_BYTES;
                uint32_t bB = sb + (2 + nh) * SUB_BYTES;
                #pragma unroll
                for (int mt = 0; mt < 4; ++mt)
                    ldsm4(af[nxt][mt], aB + swoff(arow + mt * 16, nss * 2 + ac));
                #pragma unroll
                for (int p = 0; p < 4; ++p)
                    ldsm4(bf[nxt][p], bB + swoff(brow2 + p * 16, nss * 2 + bc));
            }
            #pragma unroll
            for (int mt = 0; mt < 4; ++mt)
                #pragma unroll
                for (int p = 0; p < 4; ++p) {
                    mma16816(acc[mt][2*p],   af[cur][mt], bf[cur][p][0], bf[cur][p][1]);
                    mma16816(acc[mt][2*p+1], af[cur][mt], bf[cur][p][2], bf[cur][p][3]);
                }
        }
        __syncthreads();
    }

    // epilogue: c-fragment layout -> float2 stores
    const int r0 = brow + wm * 64 + (lane >> 2);
    const int c0 = bcol + wn * 64 + (lane & 3) * 2;
    #pragma unroll
    for (int mt = 0; mt < 4; ++mt) {
        #pragma unroll
        for (int nt = 0; nt < 8; ++nt) {
            float* p = out + (size_t)(r0 + mt * 16) * NO + c0 + nt * 8;
            *reinterpret_cast<float2*>(p) =
                make_float2(acc[mt][nt][0], acc[mt][nt][1]);
            *reinterpret_cast<float2*>(p + 8 * NO) =
                make_float2(acc[mt][nt][2], acc[mt][nt][3]);
        }
    }
}

// ---------------- launcher ---------------------------------------------------
extern "C" void kernel_launch(void* const* d_in, const int* in_sizes, int n_in,
                              void* d_out, int out_size)
{
    const float* x    = (const float*)d_in[0];   // [4096, 512]
    const float* coef = (const float*)d_in[1];   // [512, 512, 8]
    float* out        = (float*)d_out;           // [4096, 512]

    cudaFuncSetAttribute(kan_gemm, cudaFuncAttributeMaxDynamicSharedMemorySize,
                         SMEM_DYN);

    prep_kernel<<<NBLK_A + (NO * NI) / 1024, 256>>>(x, coef);

    dim3 grid(NO / 128, B_SZ / 128);             // (4, 32)
    kan_gemm<<<grid, 128, SMEM_DYN>>>(out);
}

// round 16
// speedup vs baseline: 1.0385x; 1.0235x over previous
#include <cuda_runtime.h>
#include <cuda_fp16.h>
#include <cstdint>

#define B_SZ 4096
#define NI   512
#define NO   512
#define KK   (NI*8)          // 4096

// ---------------- scratch (device globals; no allocation allowed) ----------
__device__ __half g_a[(size_t)B_SZ * KK];   // 32 MB
__device__ __half g_b[(size_t)NO * KK];     //  4 MB

// ---------------- helpers ---------------------------------------------------
__device__ __forceinline__ uint32_t smem_u32(const void* p) {
    uint32_t a;
    asm("{ .reg .u64 t; cvta.to.shared.u64 t, %1; cvt.u32.u64 %0, t; }"
        : "=r"(a) : "l"(p));
    return a;
}
__device__ __forceinline__ void cp16(uint32_t dst, const void* src) {
    asm volatile("cp.async.cg.shared.global [%0], [%1], 16;"
                 :: "r"(dst), "l"(src));
}
__device__ __forceinline__ void ldsm4(uint32_t* r, uint32_t addr) {
    asm volatile("ldmatrix.sync.aligned.m8n8.x4.shared.b16 {%0,%1,%2,%3}, [%4];"
                 : "=r"(r[0]), "=r"(r[1]), "=r"(r[2]), "=r"(r[3]) : "r"(addr));
}
__device__ __forceinline__ void mma16816(float* d, const uint32_t* a,
                                         uint32_t b0, uint32_t b1) {
    asm volatile(
        "mma.sync.aligned.m16n8k16.row.col.f32.f16.f16.f32 "
        "{%0,%1,%2,%3}, {%4,%5,%6,%7}, {%8,%9}, {%0,%1,%2,%3};"
        : "+f"(d[0]), "+f"(d[1]), "+f"(d[2]), "+f"(d[3])
        : "r"(a[0]), "r"(a[1]), "r"(a[2]), "r"(a[3]), "r"(b0), "r"(b1));
}

// fast tanh: rel err ~1e-6, far below fp16 quantization (2^-11)
__device__ __forceinline__ float fast_tanh(float x) {
    float xc = fminf(fmaxf(x, -9.0f), 9.0f);
    float e  = __expf(2.0f * xc);
    return 1.0f - __fdividef(2.0f, e + 1.0f);
}

__device__ __forceinline__ uint32_t packh2(float lo, float hi) {
    __half2 h = __float22half2_rn(make_float2(lo, hi));   // same rn rounding
    return *reinterpret_cast<uint32_t*>(&h);
}

// Jacobi orders 0..7 (alpha=beta=1) of t, packed to 4 x half2 (one uint4)
__device__ __forceinline__ void jacobi8_packed(float t, uint32_t* v) {
    float p0 = 1.0f;
    float p1 = 2.0f * t;
    float p2 = 1.875f      * t * p1 - 0.75f       * p0;
    float p3 = 1.8666667f  * t * p2 - 0.8f        * p1;
    float p4 = 1.875f      * t * p3 - 0.8333333f  * p2;
    float p5 = 1.8857143f  * t * p4 - 0.85714287f * p3;
    float p6 = 1.8958334f  * t * p5 - 0.875f      * p4;
    float p7 = 1.9047619f  * t * p6 - 0.8888889f  * p5;
    v[0] = packh2(p0, p1);
    v[1] = packh2(p2, p3);
    v[2] = packh2(p4, p5);
    v[3] = packh2(p6, p7);
}

// ---------------- phase 1: merged expand + coef convert ---------------------
// blocks [0, 2048): jacobi expand (4 elems/thread, stride-256)
// blocks [2048, 2304): coef convert (4 elems/thread, stride-256)
#define NBLK_A 2048
__global__ __launch_bounds__(256) void prep_kernel(const float* __restrict__ x,
                                                   const float* __restrict__ coef) {
    if (blockIdx.x < NBLK_A) {
        int base = blockIdx.x * 1024 + threadIdx.x;
        float t[4];
        #pragma unroll
        for (int e = 0; e < 4; ++e) t[e] = fast_tanh(x[base + e * 256]);
        #pragma unroll
        for (int e = 0; e < 4; ++e) {
            uint32_t v[4];
            jacobi8_packed(t[e], v);
            *reinterpret_cast<uint4*>(g_a + (size_t)(base + e * 256) * 8) =
                *reinterpret_cast<uint4*>(v);
        }
    } else {
        int base = (blockIdx.x - NBLK_A) * 1024 + threadIdx.x;
        #pragma unroll
        for (int e = 0; e < 4; ++e) {
            int idx = base + e * 256;
            const float4* s = reinterpret_cast<const float4*>(coef + (size_t)idx * 8);
            float4 s0 = s[0], s1 = s[1];
            uint32_t v[4];
            v[0] = packh2(s0.x, s0.y);
            v[1] = packh2(s0.z, s0.w);
            v[2] = packh2(s1.x, s1.y);
            v[3] = packh2(s1.z, s1.w);
            *reinterpret_cast<uint4*>(g_b + (size_t)idx * 8) =
                *reinterpret_cast<uint4*>(v);
        }
    }
}

// ---------------- phase 2: fp16 warp-MMA GEMM (R8 config: best measured) ----
// out[4096,512] = A[4096,4096] @ B[512,4096]^T, fp32 accumulate.
// BM=BN=128, BK=128, 256 threads = 8 warps, warp tile 32x64 (4x2 grid).
// Stage = A(32KB)+B(32KB) = 64KB as four 16KB [128x64] subtiles; 3 stages.
#define BKH 128
#define SUB_BYTES 16384
#define STAGE_BYTES 65536
#define NSTAGE 3
#define SMEM_DYN (1024 + NSTAGE * STAGE_BYTES)

// swizzled offset inside a [rows][64 fp16] subtile: 128B rows, 16B chunks
__device__ __forceinline__ uint32_t swoff(int row, int chunk) {
    return (uint32_t)(row * 128 + ((chunk ^ (row & 7)) * 16));
}

// load one 128-row x 64-fp16 subtile (16KB) with cp.async, 256 threads
__device__ __forceinline__ void load_sub(uint32_t sdst,
                                         const __half* gsrc, int tid) {
    #pragma unroll
    for (int t = 0; t < 4; ++t) {
        int idx = t * 256 + tid;           // 1024 chunks of 16B
        int row = idx >> 3, ch = idx & 7;
        cp16(sdst + swoff(row, ch),
             (const char*)(gsrc + (size_t)row * KK) + ch * 16);
    }
}
__device__ __forceinline__ void load_stage(uint32_t sb, const __half* A,
                                           const __half* B, int k0, int tid) {
    load_sub(sb,                 A + k0,      tid);
    load_sub(sb + SUB_BYTES,     A + k0 + 64, tid);
    load_sub(sb + 2 * SUB_BYTES, B + k0,      tid);
    load_sub(sb + 3 * SUB_BYTES, B + k0 + 64, tid);
}

__global__ __launch_bounds__(256, 1)
void kan_gemm(float* __restrict__ out) {
    extern __shared__ char smraw[];
    uint32_t sbase = (smem_u32(smraw) + 1023) & ~1023u;

    const int tid  = threadIdx.x;
    const int lane = tid & 31;
    const int wid  = tid >> 5;
    const int wm   = wid >> 1;          // 0..3  (32-row slice)
    const int wn   = wid & 1;           // 0..1  (64-col slice)
    const int brow = blockIdx.y * 128;
    const int bcol = blockIdx.x * 128;

    const __half* A = g_a + (size_t)brow * KK;
    const __half* B = g_b + (size_t)bcol * KK;

    float acc[2][8][4];
    #pragma unroll
    for (int i = 0; i < 2; ++i)
        #pragma unroll
        for (int j = 0; j < 8; ++j)
            #pragma unroll
            for (int c = 0; c < 4; ++c) acc[i][j][c] = 0.0f;

    // ldmatrix per-lane row / chunk-half mapping
    const int ar  = lane & 15;                        // A row within m16 tile
    const int ac  = lane >> 4;                        // A k-chunk half (0/1)
    const int br0 = ((lane >> 4) << 3) + (lane & 7);  // B row within n16 pair
    const int bc  = (lane >> 3) & 1;                  // B k-chunk half (0/1)

    // prologue: stages 0,1
    #pragma unroll
    for (int t = 0; t < NSTAGE - 1; ++t) {
        load_stage(sbase + t * STAGE_BYTES, A, B, t * BKH, tid);
        asm volatile("cp.async.commit_group;" ::: "memory");
    }

    const int NIT = KK / BKH;            // 32
    for (int kt = 0; kt < NIT; ++kt) {
        asm volatile("cp.async.wait_group %0;" :: "n"(NSTAGE - 2) : "memory");
        __syncthreads();

        // prefetch tile kt+2 into stage (kt+2)%3
        int nk = kt + NSTAGE - 1;
        if (nk < NIT) {
            load_stage(sbase + (nk % NSTAGE) * STAGE_BYTES, A, B, nk * BKH, tid);
        }
        asm volatile("cp.async.commit_group;" ::: "memory");

        // compute from stage kt%3: two 64-col k-halves x 4 k16-steps
        uint32_t sb = sbase + (kt % NSTAGE) * STAGE_BYTES;
        #pragma unroll
        for (int h = 0; h < 2; ++h) {
            uint32_t aB = sb + h * SUB_BYTES;
            uint32_t bB = sb + (2 + h) * SUB_BYTES;
            #pragma unroll
            for (int s = 0; s < 4; ++s) {
                uint32_t a[2][4];
                #pragma unroll
                for (int mt = 0; mt < 2; ++mt)
                    ldsm4(a[mt], aB + swoff(wm * 32 + mt * 16 + ar, s * 2 + ac));
                uint32_t b[4][4];
                #pragma unroll
                for (int p = 0; p < 4; ++p)
                    ldsm4(b[p], bB + swoff(wn * 64 + p * 16 + br0, s * 2 + bc));
                #pragma unroll
                for (int mt = 0; mt < 2; ++mt)
                    #pragma unroll
                    for (int p = 0; p < 4; ++p) {
                        mma16816(acc[mt][2*p],   a[mt], b[p][0], b[p][1]);
                        mma16816(acc[mt][2*p+1], a[mt], b[p][2], b[p][3]);
                    }
            }
        }
        __syncthreads();
    }

    // epilogue: c-fragment layout -> float2 stores
    const int r0 = brow + wm * 32 + (lane >> 2);
    const int c0 = bcol + wn * 64 + (lane & 3) * 2;
    #pragma unroll
    for (int mt = 0; mt < 2; ++mt) {
        #pragma unroll
        for (int nt = 0; nt < 8; ++nt) {
            float* p = out + (size_t)(r0 + mt * 16) * NO + c0 + nt * 8;
            *reinterpret_cast<float2*>(p) =
                make_float2(acc[mt][nt][0], acc[mt][nt][1]);
            *reinterpret_cast<float2*>(p + 8 * NO) =
                make_float2(acc[mt][nt][2], acc[mt][nt][3]);
        }
    }
}

// ---------------- launcher ---------------------------------------------------
extern "C" void kernel_launch(void* const* d_in, const int* in_sizes, int n_in,
                              void* d_out, int out_size)
{
    const float* x    = (const float*)d_in[0];   // [4096, 512]
    const float* coef = (const float*)d_in[1];   // [512, 512, 8]
    float* out        = (float*)d_out;           // [4096, 512]

    cudaFuncSetAttribute(kan_gemm, cudaFuncAttributeMaxDynamicSharedMemorySize,
                         SMEM_DYN);

    prep_kernel<<<NBLK_A + (NO * NI) / 1024, 256>>>(x, coef);

    dim3 grid(NO / 128, B_SZ / 128);             // (4, 32)
    kan_gemm<<<grid, 256, SMEM_DYN>>>(out);
}

// round 17
// speedup vs baseline: 1.0753x; 1.0354x over previous
#include <cuda_runtime.h>
#include <cuda_fp16.h>
#include <cstdint>

#define B_SZ 4096
#define NI   512
#define NO   512
#define KK2  3584            // 7*512: d = 1..7 planes (d=0 folded into bias)

// ---------------- scratch (device globals; no allocation allowed) ----------
__device__ __half g_a[(size_t)B_SZ * KK2];   // 28 MB
__device__ __half g_b[(size_t)NO * KK2];     //  3.5 MB
__device__ float  g_bias[NO];                // sum_i coef[j,i,0]

// ---------------- helpers ---------------------------------------------------
__device__ __forceinline__ uint32_t smem_u32(const void* p) {
    uint32_t a;
    asm("{ .reg .u64 t; cvta.to.shared.u64 t, %1; cvt.u32.u64 %0, t; }"
        : "=r"(a) : "l"(p));
    return a;
}
__device__ __forceinline__ void cp16(uint32_t dst, const void* src) {
    asm volatile("cp.async.cg.shared.global [%0], [%1], 16;"
                 :: "r"(dst), "l"(src));
}
__device__ __forceinline__ void ldsm4(uint32_t* r, uint32_t addr) {
    asm volatile("ldmatrix.sync.aligned.m8n8.x4.shared.b16 {%0,%1,%2,%3}, [%4];"
                 : "=r"(r[0]), "=r"(r[1]), "=r"(r[2]), "=r"(r[3]) : "r"(addr));
}
__device__ __forceinline__ void mma16816(float* d, const uint32_t* a,
                                         uint32_t b0, uint32_t b1) {
    asm volatile(
        "mma.sync.aligned.m16n8k16.row.col.f32.f16.f16.f32 "
        "{%0,%1,%2,%3}, {%4,%5,%6,%7}, {%8,%9}, {%0,%1,%2,%3};"
        : "+f"(d[0]), "+f"(d[1]), "+f"(d[2]), "+f"(d[3])
        : "r"(a[0]), "r"(a[1]), "r"(a[2]), "r"(a[3]), "r"(b0), "r"(b1));
}

// fast tanh: rel err ~1e-6, far below fp16 quantization (2^-11)
__device__ __forceinline__ float fast_tanh(float x) {
    float xc = fminf(fmaxf(x, -9.0f), 9.0f);
    float e  = __expf(2.0f * xc);
    return 1.0f - __fdividef(2.0f, e + 1.0f);
}

__device__ __forceinline__ uint32_t packh2(float lo, float hi) {
    __half2 h = __float22half2_rn(make_float2(lo, hi));
    return *reinterpret_cast<uint32_t*>(&h);
}

// ---------------- phase 1: expand (d-major planes) + coef + bias ------------
// A part, blocks [0, 1024): 8 consecutive (b,i) per thread. For each Jacobi
// order d (1..7) the thread's 8 values form one 16B chunk in the d-plane.
// B part, blocks [1024, 1152): coef -> fp16 d-planes + bias[j] reduction.
#define NBLK_A 1024
__global__ __launch_bounds__(256) void prep_kernel(const float* __restrict__ x,
                                                   const float* __restrict__ coef) {
    __shared__ float red[8];
    if (blockIdx.x < NBLK_A) {
        int gid  = blockIdx.x * 256 + threadIdx.x;
        int idx0 = gid * 8;
        int b  = idx0 >> 9;
        int i0 = idx0 & 511;

        const float4* xp = reinterpret_cast<const float4*>(x + idx0);
        float4 x0 = xp[0], x1 = xp[1];
        float xs[8] = {x0.x, x0.y, x0.z, x0.w, x1.x, x1.y, x1.z, x1.w};
        float t[8];
        #pragma unroll
        for (int e = 0; e < 8; ++e) t[e] = fast_tanh(xs[e]);

        __half* arow = g_a + (size_t)b * KK2 + i0;

        float prev2[8], prev1[8];
        #pragma unroll
        for (int e = 0; e < 8; ++e) { prev2[e] = 1.0f; prev1[e] = 2.0f * t[e]; }
        // emit d=1 plane
        {
            uint32_t v[4];
            #pragma unroll
            for (int q = 0; q < 4; ++q) v[q] = packh2(prev1[2*q], prev1[2*q+1]);
            *reinterpret_cast<uint4*>(arow) = *reinterpret_cast<uint4*>(v);
        }
        const float K1[6] = {1.875f, 1.8666667f, 1.875f,
                             1.8857143f, 1.8958334f, 1.9047619f};
        const float K3[6] = {0.75f, 0.8f, 0.8333333f,
                             0.85714287f, 0.875f, 0.8888889f};
        #pragma unroll
        for (int j = 0; j < 6; ++j) {      // d = j+2
            float cur[8];
            #pragma unroll
            for (int e = 0; e < 8; ++e)
                cur[e] = K1[j] * t[e] * prev1[e] - K3[j] * prev2[e];
            uint32_t v[4];
            #pragma unroll
            for (int q = 0; q < 4; ++q) v[q] = packh2(cur[2*q], cur[2*q+1]);
            *reinterpret_cast<uint4*>(arow + (j + 1) * 512) =
                *reinterpret_cast<uint4*>(v);
            #pragma unroll
            for (int e = 0; e < 8; ++e) { prev2[e] = prev1[e]; prev1[e] = cur[e]; }
        }
    } else {
        int blkb = blockIdx.x - NBLK_A;
        int gid  = blkb * 256 + threadIdx.x;
        int idx0 = gid * 8;
        int j  = idx0 >> 9;
        int i0 = idx0 & 511;

        float c[8][8];   // [e][d]
        const float4* cp = reinterpret_cast<const float4*>(coef + (size_t)idx0 * 8);
        #pragma unroll
        for (int e = 0; e < 8; ++e) {
            float4 a0 = cp[e * 2], a1 = cp[e * 2 + 1];
            c[e][0] = a0.x; c[e][1] = a0.y; c[e][2] = a0.z; c[e][3] = a0.w;
            c[e][4] = a1.x; c[e][5] = a1.y; c[e][6] = a1.z; c[e][7] = a1.w;
        }
        __half* brp = g_b + (size_t)j * KK2 + i0;
        #pragma unroll
        for (int d = 1; d < 8; ++d) {
            uint32_t v[4];
            #pragma unroll
            for (int q = 0; q < 4; ++q) v[q] = packh2(c[2*q][d], c[2*q+1][d]);
            *reinterpret_cast<uint4*>(brp + (d - 1) * 512) =
                *reinterpret_cast<uint4*>(v);
        }
        // bias[j] = sum_i coef[j,i,0]  (deterministic fixed-order reduction)
        float s = ((c[0][0] + c[1][0]) + (c[2][0] + c[3][0]))
                + ((c[4][0] + c[5][0]) + (c[6][0] + c[7][0]));
        #pragma unroll
        for (int off = 16; off > 0; off >>= 1)
            s += __shfl_xor_sync(0xffffffffu, s, off);
        int w = threadIdx.x >> 5;
        if ((threadIdx.x & 31) == 0) red[w] = s;
        __syncthreads();
        if (threadIdx.x < 4)
            g_bias[blkb * 4 + threadIdx.x] =
                red[2 * threadIdx.x] + red[2 * threadIdx.x + 1];
    }
}

// ---------------- phase 2: fp16 warp-MMA GEMM (K=3584) + bias ---------------
// out[4096,512] = A[4096,3584] @ B[512,3584]^T + bias, fp32 accumulate.
// BM=BN=128, BK=128, 256 threads = 8 warps, warp tile 32x64. 3 stages.
#define BKH 128
#define SUB_BYTES 16384
#define STAGE_BYTES 65536
#define NSTAGE 3
#define SMEM_DYN (1024 + NSTAGE * STAGE_BYTES + 512)

__device__ __forceinline__ uint32_t swoff(int row, int chunk) {
    return (uint32_t)(row * 128 + ((chunk ^ (row & 7)) * 16));
}

// load one 128-row x 64-fp16 subtile (16KB) with cp.async, 256 threads
__device__ __forceinline__ void load_sub(uint32_t sdst,
                                         const __half* gsrc, int tid) {
    #pragma unroll
    for (int t = 0; t < 4; ++t) {
        int idx = t * 256 + tid;           // 1024 chunks of 16B
        int row = idx >> 3, ch = idx & 7;
        cp16(sdst + swoff(row, ch),
             (const char*)(gsrc + (size_t)row * KK2) + ch * 16);
    }
}
__device__ __forceinline__ void load_stage(uint32_t sb, const __half* A,
                                           const __half* B, int k0, int tid) {
    load_sub(sb,                 A + k0,      tid);
    load_sub(sb + SUB_BYTES,     A + k0 + 64, tid);
    load_sub(sb + 2 * SUB_BYTES, B + k0,      tid);
    load_sub(sb + 3 * SUB_BYTES, B + k0 + 64, tid);
}

__global__ __launch_bounds__(256, 1)
void kan_gemm(float* __restrict__ out) {
    extern __shared__ char smraw[];
    uint32_t sm0   = smem_u32(smraw);
    uint32_t sbase = (sm0 + 1023) & ~1023u;
    float* sbias   = reinterpret_cast<float*>(smraw + (sbase - sm0)
                                              + NSTAGE * STAGE_BYTES);

    const int tid  = threadIdx.x;
    const int lane = tid & 31;
    const int wid  = tid >> 5;
    const int wm   = wid >> 1;          // 0..3  (32-row slice)
    const int wn   = wid & 1;           // 0..1  (64-col slice)
    const int brow = blockIdx.y * 128;
    const int bcol = blockIdx.x * 128;

    const __half* A = g_a + (size_t)brow * KK2;
    const __half* B = g_b + (size_t)bcol * KK2;

    if (tid < 128) sbias[tid] = g_bias[bcol + tid];

    float acc[2][8][4];
    #pragma unroll
    for (int i = 0; i < 2; ++i)
        #pragma unroll
        for (int j = 0; j < 8; ++j)
            #pragma unroll
            for (int c = 0; c < 4; ++c) acc[i][j][c] = 0.0f;

    // ldmatrix per-lane row / chunk-half mapping
    const int ar  = lane & 15;                        // A row within m16 tile
    const int ac  = lane >> 4;                        // A k-chunk half (0/1)
    const int br0 = ((lane >> 4) << 3) + (lane & 7);  // B row within n16 pair
    const int bc  = (lane >> 3) & 1;                  // B k-chunk half (0/1)

    // prologue: stages 0,1
    #pragma unroll
    for (int t = 0; t < NSTAGE - 1; ++t) {
        load_stage(sbase + t * STAGE_BYTES, A, B, t * BKH, tid);
        asm volatile("cp.async.commit_group;" ::: "memory");
    }

    const int NIT = KK2 / BKH;           // 28
    for (int kt = 0; kt < NIT; ++kt) {
        asm volatile("cp.async.wait_group %0;" :: "n"(NSTAGE - 2) : "memory");
        __syncthreads();

        // prefetch tile kt+2 into stage (kt+2)%3
        int nk = kt + NSTAGE - 1;
        if (nk < NIT) {
            load_stage(sbase + (nk % NSTAGE) * STAGE_BYTES, A, B, nk * BKH, tid);
        }
        asm volatile("cp.async.commit_group;" ::: "memory");

        // compute from stage kt%3: two 64-col k-halves x 4 k16-steps
        uint32_t sb = sbase + (kt % NSTAGE) * STAGE_BYTES;
        #pragma unroll
        for (int h = 0; h < 2; ++h) {
            uint32_t aB = sb + h * SUB_BYTES;
            uint32_t bB = sb + (2 + h) * SUB_BYTES;
            #pragma unroll
            for (int s = 0; s < 4; ++s) {
                uint32_t a[2][4];
                #pragma unroll
                for (int mt = 0; mt < 2; ++mt)
                    ldsm4(a[mt], aB + swoff(wm * 32 + mt * 16 + ar, s * 2 + ac));
                uint32_t b[4][4];
                #pragma unroll
                for (int p = 0; p < 4; ++p)
                    ldsm4(b[p], bB + swoff(wn * 64 + p * 16 + br0, s * 2 + bc));
                #pragma unroll
                for (int mt = 0; mt < 2; ++mt)
                    #pragma unroll
                    for (int p = 0; p < 4; ++p) {
                        mma16816(acc[mt][2*p],   a[mt], b[p][0], b[p][1]);
                        mma16816(acc[mt][2*p+1], a[mt], b[p][2], b[p][3]);
                    }
            }
        }
        __syncthreads();
    }

    // epilogue: add bias, c-fragment layout -> float2 stores
    const int r0 = brow + wm * 32 + (lane >> 2);
    const int cb = wn * 64 + (lane & 3) * 2;
    const int c0 = bcol + cb;
    #pragma unroll
    for (int nt = 0; nt < 8; ++nt) {
        float b0 = sbias[cb + nt * 8];
        float b1 = sbias[cb + nt * 8 + 1];
        #pragma unroll
        for (int mt = 0; mt < 2; ++mt) {
            float* p = out + (size_t)(r0 + mt * 16) * NO + c0 + nt * 8;
            *reinterpret_cast<float2*>(p) =
                make_float2(acc[mt][nt][0] + b0, acc[mt][nt][1] + b1);
            *reinterpret_cast<float2*>(p + 8 * NO) =
                make_float2(acc[mt][nt][2] + b0, acc[mt][nt][3] + b1);
        }
    }
}

// ---------------- launcher ---------------------------------------------------
extern "C" void kernel_launch(void* const* d_in, const int* in_sizes, int n_in,
                              void* d_out, int out_size)
{
    const float* x    = (const float*)d_in[0];   // [4096, 512]
    const float* coef = (const float*)d_in[1];   // [512, 512, 8]
    float* out        = (float*)d_out;           // [4096, 512]

    cudaFuncSetAttribute(kan_gemm, cudaFuncAttributeMaxDynamicSharedMemorySize,
                         SMEM_DYN);

    prep_kernel<<<NBLK_A + 128, 256>>>(x, coef);

    dim3 grid(NO / 128, B_SZ / 128);             // (4, 32)
    kan_gemm<<<grid, 256, SMEM_DYN>>>(out);
}